// round 1
// baseline (speedup 1.0000x reference)
#include <cuda_runtime.h>
#include <math_constants.h>

#define HID   2048
#define NH    16
#define DH    128
#define HARM  64
#define BATCH 2
#define SEQ   2048
#define MTOT  (BATCH*SEQ)   // 4096

// ---------------- scratch (static device globals; no allocs allowed) --------
__device__ float g_w[4 * HID * HARM];        // amp*cos(phase) for q,k,v,o  (2 MB)
__device__ float g_bascat[3 * HARM * HID];   // concat basis q|k|v          (1.5 MB)
__device__ float g_res[MTOT * 3 * HARM];     // resonance q|k|v             (3 MB)
__device__ float g_q[MTOT * HID];            // (B,H,S,Dh)                  (32 MB)
__device__ float g_k[MTOT * HID];
__device__ float g_v[MTOT * HID];
__device__ float g_att[MTOT * HID];          // attention out, (B,S,HID)    (32 MB)
__device__ float g_reso[MTOT * HARM];        // resonance of attn out       (1 MB)

// ---------------- small prep kernels ----------------------------------------
__global__ __launch_bounds__(256)
void build_w_kernel(const float* __restrict__ pq, const float* __restrict__ aq,
                    const float* __restrict__ pk, const float* __restrict__ ak,
                    const float* __restrict__ pv, const float* __restrict__ av,
                    const float* __restrict__ po, const float* __restrict__ ao) {
    int idx = blockIdx.x * 256 + threadIdx.x;
    if (idx >= 4 * HID * HARM) return;
    int seg = idx / (HID * HARM);
    int off = idx - seg * (HID * HARM);
    const float* ph = (seg == 0) ? pq : (seg == 1) ? pk : (seg == 2) ? pv : po;
    const float* am = (seg == 0) ? aq : (seg == 1) ? ak : (seg == 2) ? av : ao;
    g_w[idx] = am[off] * cosf(ph[off]);
}

__global__ __launch_bounds__(256)
void concat_basis_kernel(const float* __restrict__ bq, const float* __restrict__ bk,
                         const float* __restrict__ bv) {
    int idx = blockIdx.x * 256 + threadIdx.x;
    if (idx >= 3 * HARM * HID) return;
    int seg = idx / (HARM * HID);
    int off = idx - seg * (HARM * HID);
    g_bascat[idx] = (seg == 0) ? bq[off] : (seg == 1) ? bk[off] : bv[off];
}

// ---------------- generic SGEMM: C[M,N] = A[M,K] @ B[N,K]^T ------------------
// MODE 0: C row-major with leading dim ldc.
// MODE 1: C written into (B,H,S,Dh) head layout (for q/k/v).
template <int MODE>
__global__ __launch_bounds__(256)
void sgemm_abT(const float* __restrict__ A, const float* __restrict__ B,
               float* __restrict__ C, int M, int N, int K,
               int lda, int ldb, int ldc) {
    __shared__ float As[16][68];
    __shared__ float Bs[16][68];
    const int tx = threadIdx.x, ty = threadIdx.y;
    const int tid = ty * 16 + tx;
    const int m0 = blockIdx.y * 64, n0 = blockIdx.x * 64;

    float acc[4][4] = {};

    for (int k0 = 0; k0 < K; k0 += 16) {
#pragma unroll
        for (int i = 0; i < 4; i++) {
            int e = tid + i * 256;
            int r = e >> 4, kk = e & 15;
            As[kk][r] = A[(size_t)(m0 + r) * lda + k0 + kk];
            Bs[kk][r] = B[(size_t)(n0 + r) * ldb + k0 + kk];
        }
        __syncthreads();
#pragma unroll
        for (int kk = 0; kk < 16; kk++) {
            float4 a4 = *reinterpret_cast<const float4*>(&As[kk][ty * 4]);
            float4 b4 = *reinterpret_cast<const float4*>(&Bs[kk][tx * 4]);
            float av[4] = {a4.x, a4.y, a4.z, a4.w};
            float bv[4] = {b4.x, b4.y, b4.z, b4.w};
#pragma unroll
            for (int i = 0; i < 4; i++)
#pragma unroll
                for (int j = 0; j < 4; j++)
                    acc[i][j] += av[i] * bv[j];
        }
        __syncthreads();
    }

#pragma unroll
    for (int i = 0; i < 4; i++) {
        int m = m0 + ty * 4 + i;
#pragma unroll
        for (int j = 0; j < 4; j++) {
            int n = n0 + tx * 4 + j;
            if (MODE == 0) {
                C[(size_t)m * ldc + n] = acc[i][j];
            } else {
                int b = m >> 11, s = m & 2047;
                int h = n >> 7,  d = n & 127;
                C[(((size_t)(b * NH + h)) * SEQ + s) * DH + d] = acc[i][j];
            }
        }
    }
}

// ---------------- flash attention (fp32, online softmax) ---------------------
// grid: (SEQ/64 q-tiles, BATCH*NH). 256 threads (16x16).
// Shared: Qs[128][68] d-major, Ks[128][68] d-major, Vs[64][128], Ps[64][65].
#define QK_LD 68
#define SM_FLOATS (128 * QK_LD + 128 * QK_LD + 64 * 128 + 64 * 65)
#define SM_BYTES  (SM_FLOATS * 4)

__global__ __launch_bounds__(256)
void flash_attn_kernel() {
    extern __shared__ float sm[];
    float* Qs = sm;
    float* Ks = sm + 128 * QK_LD;
    float* Vs = Ks + 128 * QK_LD;
    float* Ps = Vs + 64 * 128;

    const int tx = threadIdx.x, ty = threadIdx.y;
    const int tid = ty * 16 + tx;
    const int bh = blockIdx.y;
    const int q0 = blockIdx.x * 64;

    const float* qg = g_q + (size_t)bh * SEQ * DH;
    const float* kg = g_k + (size_t)bh * SEQ * DH;
    const float* vg = g_v + (size_t)bh * SEQ * DH;

    // stage Q tile (d-major)
#pragma unroll 4
    for (int i = 0; i < 32; i++) {
        int e = tid + i * 256;
        int d = e & 127, r = e >> 7;
        Qs[d * QK_LD + r] = qg[(size_t)(q0 + r) * DH + d];
    }

    float acc[4][8] = {};
    float mrow[4], lrow[4];
#pragma unroll
    for (int i = 0; i < 4; i++) { mrow[i] = -3.0e38f; lrow[i] = 0.0f; }
    const float scale = 0.088388347648318447f;  // 1/sqrt(128)

    for (int kt = 0; kt < SEQ / 64; kt++) {
        __syncthreads();   // prev PV done before overwriting K/V/P tiles
        const float* kb = kg + (size_t)kt * 64 * DH;
        const float* vb = vg + (size_t)kt * 64 * DH;
#pragma unroll 4
        for (int i = 0; i < 32; i++) {
            int e = tid + i * 256;
            int d = e & 127, r = e >> 7;
            Ks[d * QK_LD + r] = kb[r * DH + d];
            Vs[r * DH + d]    = vb[r * DH + d];
        }
        __syncthreads();

        // S = Q K^T  (4x4 per thread)
        float s4[4][4] = {};
#pragma unroll 4
        for (int d = 0; d < 128; d++) {
            float4 a4 = *reinterpret_cast<const float4*>(&Qs[d * QK_LD + ty * 4]);
            float4 b4 = *reinterpret_cast<const float4*>(&Ks[d * QK_LD + tx * 4]);
            float av[4] = {a4.x, a4.y, a4.z, a4.w};
            float bv[4] = {b4.x, b4.y, b4.z, b4.w};
#pragma unroll
            for (int i = 0; i < 4; i++)
#pragma unroll
                for (int j = 0; j < 4; j++)
                    s4[i][j] += av[i] * bv[j];
        }

        // row max across the 16 lanes that share each row
        float rawmax[4];
#pragma unroll
        for (int i = 0; i < 4; i++)
            rawmax[i] = fmaxf(fmaxf(s4[i][0], s4[i][1]), fmaxf(s4[i][2], s4[i][3]));
#pragma unroll
        for (int off = 1; off < 16; off <<= 1)
#pragma unroll
            for (int i = 0; i < 4; i++)
                rawmax[i] = fmaxf(rawmax[i], __shfl_xor_sync(0xffffffffu, rawmax[i], off));

        float nm[4], corr[4], rsum[4];
#pragma unroll
        for (int i = 0; i < 4; i++) {
            nm[i] = fmaxf(mrow[i], rawmax[i] * scale);
            corr[i] = __expf(mrow[i] - nm[i]);
            mrow[i] = nm[i];
            rsum[i] = 0.0f;
        }
#pragma unroll
        for (int i = 0; i < 4; i++)
#pragma unroll
            for (int j = 0; j < 4; j++) {
                float p = __expf(s4[i][j] * scale - nm[i]);
                Ps[(tx * 4 + j) * 65 + ty * 4 + i] = p;
                rsum[i] += p;
            }
#pragma unroll
        for (int off = 1; off < 16; off <<= 1)
#pragma unroll
            for (int i = 0; i < 4; i++)
                rsum[i] += __shfl_xor_sync(0xffffffffu, rsum[i], off);
#pragma unroll
        for (int i = 0; i < 4; i++) {
            lrow[i] = lrow[i] * corr[i] + rsum[i];
#pragma unroll
            for (int j = 0; j < 8; j++) acc[i][j] *= corr[i];
        }
        __syncthreads();   // P visible to all

        // O += P V  (4x8 per thread)
#pragma unroll 4
        for (int kk = 0; kk < 64; kk++) {
            float p0 = Ps[kk * 65 + ty * 4 + 0];
            float p1 = Ps[kk * 65 + ty * 4 + 1];
            float p2 = Ps[kk * 65 + ty * 4 + 2];
            float p3 = Ps[kk * 65 + ty * 4 + 3];
            float4 v0 = *reinterpret_cast<const float4*>(&Vs[kk * DH + tx * 8]);
            float4 v1 = *reinterpret_cast<const float4*>(&Vs[kk * DH + tx * 8 + 4]);
            float vv[8] = {v0.x, v0.y, v0.z, v0.w, v1.x, v1.y, v1.z, v1.w};
#pragma unroll
            for (int j = 0; j < 8; j++) {
                acc[0][j] += p0 * vv[j];
                acc[1][j] += p1 * vv[j];
                acc[2][j] += p2 * vv[j];
                acc[3][j] += p3 * vv[j];
            }
        }
    }

    // epilogue: normalize and scatter to (B,S,HID)
    const int b = bh >> 4, h = bh & 15;
#pragma unroll
    for (int i = 0; i < 4; i++) {
        float inv = 1.0f / lrow[i];
        int srow = q0 + ty * 4 + i;
        float* op = g_att + ((size_t)(b * SEQ + srow)) * HID + h * DH + tx * 8;
        float4 o0 = {acc[i][0] * inv, acc[i][1] * inv, acc[i][2] * inv, acc[i][3] * inv};
        float4 o1 = {acc[i][4] * inv, acc[i][5] * inv, acc[i][6] * inv, acc[i][7] * inv};
        *reinterpret_cast<float4*>(op)     = o0;
        *reinterpret_cast<float4*>(op + 4) = o1;
    }
}

// ---------------- launcher ----------------------------------------------------
extern "C" void kernel_launch(void* const* d_in, const int* in_sizes, int n_in,
                              void* d_out, int out_size) {
    const float* x  = (const float*)d_in[0];
    const float* bq = (const float*)d_in[1];
    const float* pq = (const float*)d_in[2];
    const float* aq = (const float*)d_in[3];
    const float* bk = (const float*)d_in[4];
    const float* pk = (const float*)d_in[5];
    const float* ak = (const float*)d_in[6];
    const float* bv = (const float*)d_in[7];
    const float* pv = (const float*)d_in[8];
    const float* av = (const float*)d_in[9];
    const float* bo = (const float*)d_in[10];
    const float* po = (const float*)d_in[11];
    const float* ao = (const float*)d_in[12];
    float* out = (float*)d_out;

    float *w, *bascat, *res, *q, *k, *v, *att, *reso;
    cudaGetSymbolAddress((void**)&w,      g_w);
    cudaGetSymbolAddress((void**)&bascat, g_bascat);
    cudaGetSymbolAddress((void**)&res,    g_res);
    cudaGetSymbolAddress((void**)&q,      g_q);
    cudaGetSymbolAddress((void**)&k,      g_k);
    cudaGetSymbolAddress((void**)&v,      g_v);
    cudaGetSymbolAddress((void**)&att,    g_att);
    cudaGetSymbolAddress((void**)&reso,   g_reso);

    build_w_kernel<<<(4 * HID * HARM + 255) / 256, 256>>>(pq, aq, pk, ak, pv, av, po, ao);
    concat_basis_kernel<<<(3 * HARM * HID + 255) / 256, 256>>>(bq, bk, bv);

    dim3 thr(16, 16);

    // resonance for q|k|v: (4096 x 192) = x (4096x2048) @ bascat^T (192x2048)
    sgemm_abT<0><<<dim3(192 / 64, MTOT / 64), thr>>>(x, bascat, res,
                                                     MTOT, 3 * HARM, HID, HID, HID, 3 * HARM);

    // q/k/v: (4096 x 2048) = res_part (4096x64) @ w^T (2048x64), head-layout store
    sgemm_abT<1><<<dim3(HID / 64, MTOT / 64), thr>>>(res + 0,        w + 0 * HID * HARM, q,
                                                     MTOT, HID, HARM, 3 * HARM, HARM, 0);
    sgemm_abT<1><<<dim3(HID / 64, MTOT / 64), thr>>>(res + HARM,     w + 1 * HID * HARM, k,
                                                     MTOT, HID, HARM, 3 * HARM, HARM, 0);
    sgemm_abT<1><<<dim3(HID / 64, MTOT / 64), thr>>>(res + 2 * HARM, w + 2 * HID * HARM, v,
                                                     MTOT, HID, HARM, 3 * HARM, HARM, 0);

    cudaFuncSetAttribute(flash_attn_kernel,
                         cudaFuncAttributeMaxDynamicSharedMemorySize, SM_BYTES);
    flash_attn_kernel<<<dim3(SEQ / 64, BATCH * NH), thr, SM_BYTES>>>();

    // output holo linear
    sgemm_abT<0><<<dim3(1, MTOT / 64), thr>>>(att, bo, reso,
                                              MTOT, HARM, HID, HID, HID, HARM);
    sgemm_abT<0><<<dim3(HID / 64, MTOT / 64), thr>>>(reso, w + 3 * HID * HARM, out,
                                                     MTOT, HID, HARM, HARM, HARM, HID);
}

// round 6
// speedup vs baseline: 2.7674x; 2.7674x over previous
#include <cuda_runtime.h>
#include <cuda_bf16.h>
#include <cstdint>

#define HID   2048
#define NH    16
#define DH    128
#define HARM  64
#define BATCH 2
#define SEQ   2048
#define MTOT  (BATCH*SEQ)   // 4096

// ---------------- scratch (static device globals; no allocs allowed) --------
__device__ float g_w[4 * HID * HARM];
__device__ float g_bascat[3 * HARM * HID];
__device__ float g_res[MTOT * 3 * HARM];
__device__ __align__(256) __nv_bfloat16 g_qh[MTOT * HID];
__device__ __align__(256) __nv_bfloat16 g_ql[MTOT * HID];
__device__ __align__(256) __nv_bfloat16 g_kh[MTOT * HID];
__device__ __align__(256) __nv_bfloat16 g_kl[MTOT * HID];
__device__ __align__(256) __nv_bfloat16 g_vth[MTOT * HID];   // (bh, d, s)
__device__ __align__(256) __nv_bfloat16 g_vtl[MTOT * HID];
__device__ __align__(256) float g_att[MTOT * HID];
__device__ float g_reso[MTOT * HARM];

// ---------------- PTX helpers (portable: sm_80+ features only) ---------------
__device__ __forceinline__ uint32_t smem_u32(const void* p) {
    uint32_t a;
    asm("{ .reg .u64 t; cvta.to.shared.u64 t, %1; cvt.u32.u64 %0, t; }" : "=r"(a) : "l"(p));
    return a;
}
__device__ __forceinline__ void ldsm4(uint32_t r[4], uint32_t addr) {
    asm volatile("ldmatrix.sync.aligned.m8n8.x4.shared.b16 {%0,%1,%2,%3}, [%4];"
                 : "=r"(r[0]), "=r"(r[1]), "=r"(r[2]), "=r"(r[3]) : "r"(addr));
}
__device__ __forceinline__ void mma16816(float d[4], const uint32_t a[4],
                                         uint32_t b0, uint32_t b1) {
    asm volatile("mma.sync.aligned.m16n8k16.row.col.f32.bf16.bf16.f32 "
                 "{%0,%1,%2,%3}, {%4,%5,%6,%7}, {%8,%9}, {%0,%1,%2,%3};"
                 : "+f"(d[0]), "+f"(d[1]), "+f"(d[2]), "+f"(d[3])
                 : "r"(a[0]), "r"(a[1]), "r"(a[2]), "r"(a[3]), "r"(b0), "r"(b1));
}
__device__ __forceinline__ void cpasync16(uint32_t dst, const void* src) {
    asm volatile("cp.async.cg.shared.global [%0], [%1], 16;" :: "r"(dst), "l"(src));
}
#define CP_COMMIT() asm volatile("cp.async.commit_group;" ::: "memory")
#define CP_WAIT0()  asm volatile("cp.async.wait_group 0;" ::: "memory")

__device__ __forceinline__ float fast_exp2(float x) {
    float y;
    asm("ex2.approx.ftz.f32 %0, %1;" : "=f"(y) : "f"(x));
    return y;
}
__device__ __forceinline__ uint32_t cvt2(float hi, float lo) {   // pack {hi,lo} -> bf16x2
    uint32_t r;
    asm("cvt.rn.bf16x2.f32 %0, %1, %2;" : "=r"(r) : "f"(hi), "f"(lo));
    return r;
}
__device__ __forceinline__ float bfhi_f(uint32_t p) { return __uint_as_float(p & 0xffff0000u); }
__device__ __forceinline__ float bflo_f(uint32_t p) { return __uint_as_float(p << 16); }

// ---------------- small prep kernels ----------------------------------------
__global__ __launch_bounds__(256)
void build_w_kernel(const float* __restrict__ pq, const float* __restrict__ aq,
                    const float* __restrict__ pk, const float* __restrict__ ak,
                    const float* __restrict__ pv, const float* __restrict__ av,
                    const float* __restrict__ po, const float* __restrict__ ao) {
    int idx = blockIdx.x * 256 + threadIdx.x;
    if (idx >= 4 * HID * HARM) return;
    int seg = idx / (HID * HARM);
    int off = idx - seg * (HID * HARM);
    const float* ph = (seg == 0) ? pq : (seg == 1) ? pk : (seg == 2) ? pv : po;
    const float* am = (seg == 0) ? aq : (seg == 1) ? ak : (seg == 2) ? av : ao;
    g_w[idx] = am[off] * cosf(ph[off]);
}

__global__ __launch_bounds__(256)
void concat_basis_kernel(const float* __restrict__ bq, const float* __restrict__ bk,
                         const float* __restrict__ bv) {
    int idx = blockIdx.x * 256 + threadIdx.x;
    if (idx >= 3 * HARM * HID) return;
    int seg = idx / (HARM * HID);
    int off = idx - seg * (HARM * HID);
    g_bascat[idx] = (seg == 0) ? bq[off] : (seg == 1) ? bk[off] : bv[off];
}

// ---------------- generic SGEMM: C[M,N] = A[M,K] @ B[N,K]^T (fp32 out) -------
__global__ __launch_bounds__(256)
void sgemm_abT(const float* __restrict__ A, const float* __restrict__ B,
               float* __restrict__ C, int M, int N, int K,
               int lda, int ldb, int ldc) {
    __shared__ float As[16][68];
    __shared__ float Bs[16][68];
    const int tx = threadIdx.x, ty = threadIdx.y;
    const int tid = ty * 16 + tx;
    const int m0 = blockIdx.y * 64, n0 = blockIdx.x * 64;
    float acc[4][4] = {};
    for (int k0 = 0; k0 < K; k0 += 16) {
#pragma unroll
        for (int i = 0; i < 4; i++) {
            int e = tid + i * 256;
            int r = e >> 4, kk = e & 15;
            As[kk][r] = A[(size_t)(m0 + r) * lda + k0 + kk];
            Bs[kk][r] = B[(size_t)(n0 + r) * ldb + k0 + kk];
        }
        __syncthreads();
#pragma unroll
        for (int kk = 0; kk < 16; kk++) {
            float4 a4 = *reinterpret_cast<const float4*>(&As[kk][ty * 4]);
            float4 b4 = *reinterpret_cast<const float4*>(&Bs[kk][tx * 4]);
            float av[4] = {a4.x, a4.y, a4.z, a4.w};
            float bv[4] = {b4.x, b4.y, b4.z, b4.w};
#pragma unroll
            for (int i = 0; i < 4; i++)
#pragma unroll
                for (int j = 0; j < 4; j++)
                    acc[i][j] += av[i] * bv[j];
        }
        __syncthreads();
    }
#pragma unroll
    for (int i = 0; i < 4; i++) {
        int m = m0 + ty * 4 + i;
#pragma unroll
        for (int j = 0; j < 4; j++)
            C[(size_t)m * ldc + n0 + tx * 4 + j] = acc[i][j];
    }
}

// ---------------- projection GEMM -> bf16 hi/lo ------------------------------
// MODE 1: write (b,h,s,d)  [for Q,K]    MODE 2: write (b,h,d,s)  [for V^T]
template <int MODE>
__global__ __launch_bounds__(256)
void sgemm_proj(const float* __restrict__ A, const float* __restrict__ B,
                __nv_bfloat16* __restrict__ Ch, __nv_bfloat16* __restrict__ Cl,
                int lda) {
    __shared__ float As[16][68];
    __shared__ float Bs[16][68];
    const int tx = threadIdx.x, ty = threadIdx.y;
    const int tid = ty * 16 + tx;
    const int m0 = blockIdx.y * 64, n0 = blockIdx.x * 64;
    float acc[4][4] = {};
    for (int k0 = 0; k0 < HARM; k0 += 16) {
#pragma unroll
        for (int i = 0; i < 4; i++) {
            int e = tid + i * 256;
            int r = e >> 4, kk = e & 15;
            As[kk][r] = A[(size_t)(m0 + r) * lda + k0 + kk];
            Bs[kk][r] = B[(size_t)(n0 + r) * HARM + k0 + kk];
        }
        __syncthreads();
#pragma unroll
        for (int kk = 0; kk < 16; kk++) {
            float4 a4 = *reinterpret_cast<const float4*>(&As[kk][ty * 4]);
            float4 b4 = *reinterpret_cast<const float4*>(&Bs[kk][tx * 4]);
            float av[4] = {a4.x, a4.y, a4.z, a4.w};
            float bv[4] = {b4.x, b4.y, b4.z, b4.w};
#pragma unroll
            for (int i = 0; i < 4; i++)
#pragma unroll
                for (int j = 0; j < 4; j++)
                    acc[i][j] += av[i] * bv[j];
        }
        __syncthreads();
    }
#pragma unroll
    for (int i = 0; i < 4; i++) {
        int m = m0 + ty * 4 + i;
        int b = m >> 11, s = m & 2047;
#pragma unroll
        for (int j = 0; j < 4; j++) {
            int n = n0 + tx * 4 + j;
            int h = n >> 7, d = n & 127;
            size_t idx;
            if (MODE == 1) idx = (((size_t)(b * NH + h)) * SEQ + s) * DH + d;
            else           idx = (((size_t)(b * NH + h)) * DH + d) * SEQ + s;
            float x = acc[i][j];
            __nv_bfloat16 hv = __float2bfloat16(x);
            __nv_bfloat16 lv = __float2bfloat16(x - __bfloat162float(hv));
            Ch[idx] = hv;
            Cl[idx] = lv;
        }
    }
}

// ---------------- mma.sync flash attention (online softmax) ------------------
// grid (SEQ/128, BATCH*NH), 256 threads (8 warps x 16 q-rows). BK=64.
#define BQ 128
#define BK 64
#define OFF_QS 0                 // Qh [128x256B swz] then Ql
#define OFF_B0 65536             // double buffers: Kh,Kl,VTh,VTl (16KB each)
#define BUFSZ  65536
#define FA_SMEM (OFF_B0 + 2*BUFSZ)   // 196608

__device__ __forceinline__ void prefetch_tile(uint32_t sb, int buf, int bh, int kt, int tid) {
    const uint32_t base = sb + OFF_B0 + buf * BUFSZ;
    const __nv_bfloat16* kh = g_kh + ((size_t)bh * SEQ + kt * BK) * DH;
    const __nv_bfloat16* kl = g_kl + ((size_t)bh * SEQ + kt * BK) * DH;
#pragma unroll
    for (int i = 0; i < 4; i++) {
        int e = tid + i * 256;
        int row = e >> 4, cb = e & 15;                  // 64 rows x 16 chunks
        uint32_t off = row * 256 + ((cb ^ (row & 7)) << 4);
        cpasync16(base + off,          kh + row * DH + cb * 8);
        cpasync16(base + 16384 + off,  kl + row * DH + cb * 8);
    }
    const __nv_bfloat16* vh = g_vth + (size_t)bh * DH * SEQ + kt * BK;
    const __nv_bfloat16* vl = g_vtl + (size_t)bh * DH * SEQ + kt * BK;
#pragma unroll
    for (int i = 0; i < 4; i++) {
        int e = tid + i * 256;
        int row = e >> 3, cb = e & 7;                   // 128 rows x 8 chunks
        uint32_t off = row * 128 + ((cb ^ (row & 7)) << 4);
        cpasync16(base + 32768 + off, vh + (size_t)row * SEQ + cb * 8);
        cpasync16(base + 49152 + off, vl + (size_t)row * SEQ + cb * 8);
    }
    CP_COMMIT();
}

__global__ __launch_bounds__(256, 1)
void flash_mma_kernel() {
    extern __shared__ char sm[];
    const uint32_t sb = smem_u32(sm);
    const int tid = threadIdx.x;
    const int lane = tid & 31, w = tid >> 5;
    const int bh = blockIdx.y;
    const int q0 = blockIdx.x * BQ;
    const int b = bh >> 4, h = bh & 15;
    const float K2 = 0.12751742f;   // (1/sqrt(128)) * log2(e)

    // ---- stage Q hi/lo (swizzled) ----
    {
        const __nv_bfloat16* qhg = g_qh + ((size_t)bh * SEQ + q0) * DH;
        const __nv_bfloat16* qlg = g_ql + ((size_t)bh * SEQ + q0) * DH;
#pragma unroll
        for (int i = 0; i < 8; i++) {
            int e = tid + i * 256;
            int row = e >> 4, cb = e & 15;
            uint32_t off = OFF_QS + row * 256 + ((cb ^ (row & 7)) << 4);
            *reinterpret_cast<uint4*>(sm + off) =
                *reinterpret_cast<const uint4*>(qhg + row * DH + cb * 8);
            *reinterpret_cast<uint4*>(sm + off + 32768) =
                *reinterpret_cast<const uint4*>(qlg + row * DH + cb * 8);
        }
    }
    prefetch_tile(sb, 0, bh, 0, tid);
    __syncthreads();

    // ---- Q fragments (resident) ----
    uint32_t qfh[8][4], qfl[8][4];
    const int m0 = 16 * w;
#pragma unroll
    for (int ks = 0; ks < 8; ks++) {
        int row = m0 + (lane & 15);
        int cb = 2 * ks + (lane >> 4);
        uint32_t a = sb + OFF_QS + row * 256 + ((cb ^ (row & 7)) << 4);
        ldsm4(qfh[ks], a);
        ldsm4(qfl[ks], a + 32768);
    }

    float O[16][4] = {};
    float rs0 = 0.0f, rs1 = 0.0f;
    float mx0 = -3.0e38f, mx1 = -3.0e38f;   // running row max (scaled, log2 domain)
    int buf = 0;

    for (int kt = 0; kt < SEQ / BK; kt++) {
        CP_WAIT0();
        __syncthreads();
        if (kt + 1 < SEQ / BK) prefetch_tile(sb, buf ^ 1, bh, kt + 1, tid);

        const uint32_t kb = sb + OFF_B0 + buf * BUFSZ;

        // ---- S = Q K^T (hi*hi + lo*hi + hi*lo) ----
        float S[8][4] = {};
#pragma unroll
        for (int ks = 0; ks < 8; ks++) {
#pragma unroll
            for (int np = 0; np < 4; np++) {
                int row = 16 * np + (lane & 15);
                int cb = 2 * ks + (lane >> 4);
                uint32_t off = row * 256 + ((cb ^ (row & 7)) << 4);
                uint32_t fh[4], fl[4];
                ldsm4(fh, kb + off);
                ldsm4(fl, kb + 16384 + off);
                mma16816(S[2 * np],     qfh[ks], fh[0], fh[2]);
                mma16816(S[2 * np + 1], qfh[ks], fh[1], fh[3]);
                mma16816(S[2 * np],     qfl[ks], fh[0], fh[2]);
                mma16816(S[2 * np + 1], qfl[ks], fh[1], fh[3]);
                mma16816(S[2 * np],     qfh[ks], fl[0], fl[2]);
                mma16816(S[2 * np + 1], qfh[ks], fl[1], fl[3]);
            }
        }

        // ---- online softmax: row max, rescale, exp2 ----
        float tm0 = -3.0e38f, tm1 = -3.0e38f;
#pragma unroll
        for (int t = 0; t < 8; t++) {
            tm0 = fmaxf(tm0, fmaxf(S[t][0], S[t][1]));
            tm1 = fmaxf(tm1, fmaxf(S[t][2], S[t][3]));
        }
        tm0 = fmaxf(tm0, __shfl_xor_sync(0xffffffffu, tm0, 1));
        tm0 = fmaxf(tm0, __shfl_xor_sync(0xffffffffu, tm0, 2));
        tm1 = fmaxf(tm1, __shfl_xor_sync(0xffffffffu, tm1, 1));
        tm1 = fmaxf(tm1, __shfl_xor_sync(0xffffffffu, tm1, 2));

        float nm0 = fmaxf(mx0, tm0 * K2);
        float nm1 = fmaxf(mx1, tm1 * K2);
        float c0 = fast_exp2(mx0 - nm0);
        float c1 = fast_exp2(mx1 - nm1);
        mx0 = nm0; mx1 = nm1;

        float ls0 = 0.0f, ls1 = 0.0f;
#pragma unroll
        for (int t = 0; t < 8; t++) {
            float e0 = fast_exp2(S[t][0] * K2 - nm0);
            float e1 = fast_exp2(S[t][1] * K2 - nm0);
            float e2 = fast_exp2(S[t][2] * K2 - nm1);
            float e3 = fast_exp2(S[t][3] * K2 - nm1);
            ls0 += e0 + e1;
            ls1 += e2 + e3;
            S[t][0] = e0; S[t][1] = e1; S[t][2] = e2; S[t][3] = e3;
        }
        rs0 = rs0 * c0 + ls0;
        rs1 = rs1 * c1 + ls1;
#pragma unroll
        for (int t = 0; t < 16; t++) {
            O[t][0] *= c0; O[t][1] *= c0;
            O[t][2] *= c1; O[t][3] *= c1;
        }

        // ---- O += P V (P stays in registers as A-fragments) ----
#pragma unroll
        for (int ks2 = 0; ks2 < 4; ks2++) {
            uint32_t ph[4], pl[4];
            ph[0] = cvt2(S[2 * ks2][1],     S[2 * ks2][0]);
            ph[1] = cvt2(S[2 * ks2][3],     S[2 * ks2][2]);
            ph[2] = cvt2(S[2 * ks2 + 1][1], S[2 * ks2 + 1][0]);
            ph[3] = cvt2(S[2 * ks2 + 1][3], S[2 * ks2 + 1][2]);
            pl[0] = cvt2(S[2 * ks2][1]     - bfhi_f(ph[0]), S[2 * ks2][0]     - bflo_f(ph[0]));
            pl[1] = cvt2(S[2 * ks2][3]     - bfhi_f(ph[1]), S[2 * ks2][2]     - bflo_f(ph[1]));
            pl[2] = cvt2(S[2 * ks2 + 1][1] - bfhi_f(ph[2]), S[2 * ks2 + 1][0] - bflo_f(ph[2]));
            pl[3] = cvt2(S[2 * ks2 + 1][3] - bfhi_f(ph[3]), S[2 * ks2 + 1][2] - bflo_f(ph[3]));
#pragma unroll
            for (int dp = 0; dp < 8; dp++) {
                int row = 16 * dp + (lane & 15);
                int cb = 2 * ks2 + (lane >> 4);
                uint32_t off = row * 128 + ((cb ^ (row & 7)) << 4);
                uint32_t vh[4], vl[4];
                ldsm4(vh, kb + 32768 + off);
                ldsm4(vl, kb + 49152 + off);
                mma16816(O[2 * dp],     ph, vh[0], vh[2]);
                mma16816(O[2 * dp + 1], ph, vh[1], vh[3]);
                mma16816(O[2 * dp],     ph, vl[0], vl[2]);
                mma16816(O[2 * dp + 1], ph, vl[1], vl[3]);
                mma16816(O[2 * dp],     pl, vh[0], vh[2]);
                mma16816(O[2 * dp + 1], pl, vh[1], vh[3]);
            }
        }
        buf ^= 1;
    }

    // ---- epilogue: per-row normalize, store (B,S,HID) ----
    rs0 += __shfl_xor_sync(0xffffffffu, rs0, 1);
    rs0 += __shfl_xor_sync(0xffffffffu, rs0, 2);
    rs1 += __shfl_xor_sync(0xffffffffu, rs1, 1);
    rs1 += __shfl_xor_sync(0xffffffffu, rs1, 2);
    const float inv0 = 1.0f / rs0;
    const float inv1 = 1.0f / rs1;

    const int r0g = q0 + 16 * w + (lane >> 2);
    float* op  = g_att + ((size_t)(b * SEQ) + r0g) * HID + h * DH + (lane & 3) * 2;
    float* op2 = op + 8 * HID;
#pragma unroll
    for (int t = 0; t < 16; t++) {
        float2 v0 = make_float2(O[t][0] * inv0, O[t][1] * inv0);
        float2 v1 = make_float2(O[t][2] * inv1, O[t][3] * inv1);
        *reinterpret_cast<float2*>(op  + 8 * t) = v0;
        *reinterpret_cast<float2*>(op2 + 8 * t) = v1;
    }
}

// ---------------- launcher ----------------------------------------------------
extern "C" void kernel_launch(void* const* d_in, const int* in_sizes, int n_in,
                              void* d_out, int out_size) {
    const float* x  = (const float*)d_in[0];
    const float* bq = (const float*)d_in[1];
    const float* pq = (const float*)d_in[2];
    const float* aq = (const float*)d_in[3];
    const float* bk = (const float*)d_in[4];
    const float* pk = (const float*)d_in[5];
    const float* ak = (const float*)d_in[6];
    const float* bv = (const float*)d_in[7];
    const float* pv = (const float*)d_in[8];
    const float* av = (const float*)d_in[9];
    const float* bo = (const float*)d_in[10];
    const float* po = (const float*)d_in[11];
    const float* ao = (const float*)d_in[12];
    float* out = (float*)d_out;

    float *w, *bascat, *res, *att, *reso;
    __nv_bfloat16 *qh, *ql, *kh, *kl, *vth, *vtl;
    cudaGetSymbolAddress((void**)&w,      g_w);
    cudaGetSymbolAddress((void**)&bascat, g_bascat);
    cudaGetSymbolAddress((void**)&res,    g_res);
    cudaGetSymbolAddress((void**)&qh,     g_qh);
    cudaGetSymbolAddress((void**)&ql,     g_ql);
    cudaGetSymbolAddress((void**)&kh,     g_kh);
    cudaGetSymbolAddress((void**)&kl,     g_kl);
    cudaGetSymbolAddress((void**)&vth,    g_vth);
    cudaGetSymbolAddress((void**)&vtl,    g_vtl);
    cudaGetSymbolAddress((void**)&att,    g_att);
    cudaGetSymbolAddress((void**)&reso,   g_reso);

    build_w_kernel<<<(4 * HID * HARM + 255) / 256, 256>>>(pq, aq, pk, ak, pv, av, po, ao);
    concat_basis_kernel<<<(3 * HARM * HID + 255) / 256, 256>>>(bq, bk, bv);

    dim3 thr(16, 16);

    // resonance q|k|v: (4096 x 192)
    sgemm_abT<<<dim3(192 / 64, MTOT / 64), thr>>>(x, bascat, res,
                                                  MTOT, 3 * HARM, HID, HID, HID, 3 * HARM);

    // projections -> bf16 hi/lo (Q,K in (b,h,s,d); V transposed to (b,h,d,s))
    sgemm_proj<1><<<dim3(HID / 64, MTOT / 64), thr>>>(res + 0,        w + 0 * HID * HARM, qh, ql, 3 * HARM);
    sgemm_proj<1><<<dim3(HID / 64, MTOT / 64), thr>>>(res + HARM,     w + 1 * HID * HARM, kh, kl, 3 * HARM);
    sgemm_proj<2><<<dim3(HID / 64, MTOT / 64), thr>>>(res + 2 * HARM, w + 2 * HID * HARM, vth, vtl, 3 * HARM);

    cudaFuncSetAttribute(flash_mma_kernel,
                         cudaFuncAttributeMaxDynamicSharedMemorySize, FA_SMEM);
    flash_mma_kernel<<<dim3(SEQ / BQ, BATCH * NH), 256, FA_SMEM>>>();

    // output holo linear
    sgemm_abT<<<dim3(1, MTOT / 64), thr>>>(att, bo, reso,
                                           MTOT, HARM, HID, HID, HID, HARM);
    sgemm_abT<<<dim3(HID / 64, MTOT / 64), thr>>>(reso, w + 3 * HID * HARM, out,
                                                  MTOT, HID, HARM, HARM, HARM, HID);
}

// round 7
// speedup vs baseline: 5.0160x; 1.8125x over previous
#include <cuda_runtime.h>
#include <cuda_bf16.h>
#include <cstdint>

#define HID   2048
#define NH    16
#define DH    128
#define HARM  64
#define BATCH 2
#define SEQ   2048
#define MTOT  (BATCH*SEQ)   // 4096

// ---------------- scratch (static device globals; no allocs allowed) --------
__device__ float g_w[4 * HID * HARM];          // amp*cos(phase) q,k,v,o
__device__ float g_bascat[3 * HARM * HID];     // concat basis q|k|v
__device__ float g_res[MTOT * 3 * HARM];       // resonances q|k|v (fp32)
__device__ float g_G[NH * HARM * HARM];        // Gt[h*64+j][k] = (Wq_h^T Wk_h)[k,j]
__device__ float g_C[HARM * NH * HARM];        // C[j][h*64+i] = (Bo_h Wv_h)[j,i]
__device__ __align__(256) __nv_bfloat16 g_th[MTOT * NH * HARM];  // T hi (b,h,s,64)
__device__ __align__(256) __nv_bfloat16 g_tl[MTOT * NH * HARM];
__device__ __align__(256) __nv_bfloat16 g_rkh[MTOT * HARM];      // Res_k hi (b,s,64)
__device__ __align__(256) __nv_bfloat16 g_rkl[MTOT * HARM];
__device__ __align__(256) __nv_bfloat16 g_rvh[MTOT * HARM];      // Res_v^T hi (b,64,s)
__device__ __align__(256) __nv_bfloat16 g_rvl[MTOT * HARM];
__device__ __align__(256) float g_u[MTOT * NH * HARM];           // U (b,s,h,64) fp32
__device__ float g_reso[MTOT * HARM];

// ---------------- PTX helpers (portable: sm_80+ features only) ---------------
__device__ __forceinline__ uint32_t smem_u32(const void* p) {
    uint32_t a;
    asm("{ .reg .u64 t; cvta.to.shared.u64 t, %1; cvt.u32.u64 %0, t; }" : "=r"(a) : "l"(p));
    return a;
}
__device__ __forceinline__ void ldsm4(uint32_t r[4], uint32_t addr) {
    asm volatile("ldmatrix.sync.aligned.m8n8.x4.shared.b16 {%0,%1,%2,%3}, [%4];"
                 : "=r"(r[0]), "=r"(r[1]), "=r"(r[2]), "=r"(r[3]) : "r"(addr));
}
__device__ __forceinline__ void mma16816(float d[4], const uint32_t a[4],
                                         uint32_t b0, uint32_t b1) {
    asm volatile("mma.sync.aligned.m16n8k16.row.col.f32.bf16.bf16.f32 "
                 "{%0,%1,%2,%3}, {%4,%5,%6,%7}, {%8,%9}, {%0,%1,%2,%3};"
                 : "+f"(d[0]), "+f"(d[1]), "+f"(d[2]), "+f"(d[3])
                 : "r"(a[0]), "r"(a[1]), "r"(a[2]), "r"(a[3]), "r"(b0), "r"(b1));
}
__device__ __forceinline__ void cpasync16(uint32_t dst, const void* src) {
    asm volatile("cp.async.cg.shared.global [%0], [%1], 16;" :: "r"(dst), "l"(src));
}
#define CP_COMMIT() asm volatile("cp.async.commit_group;" ::: "memory")
#define CP_WAIT0()  asm volatile("cp.async.wait_group 0;" ::: "memory")

__device__ __forceinline__ float fast_exp2(float x) {
    float y;
    asm("ex2.approx.ftz.f32 %0, %1;" : "=f"(y) : "f"(x));
    return y;
}
__device__ __forceinline__ uint32_t cvt2(float hi, float lo) {   // pack {hi,lo} -> bf16x2
    uint32_t r;
    asm("cvt.rn.bf16x2.f32 %0, %1, %2;" : "=r"(r) : "f"(hi), "f"(lo));
    return r;
}
__device__ __forceinline__ float bfhi_f(uint32_t p) { return __uint_as_float(p & 0xffff0000u); }
__device__ __forceinline__ float bflo_f(uint32_t p) { return __uint_as_float(p << 16); }

// ---------------- prep: w = amp*cos(phase), bascat -----------------------------
__global__ __launch_bounds__(256)
void prep_kernel(const float* __restrict__ pq, const float* __restrict__ aq,
                 const float* __restrict__ pk, const float* __restrict__ ak,
                 const float* __restrict__ pv, const float* __restrict__ av,
                 const float* __restrict__ po, const float* __restrict__ ao,
                 const float* __restrict__ bq, const float* __restrict__ bk,
                 const float* __restrict__ bv) {
    int idx = blockIdx.x * 256 + threadIdx.x;
    if (idx < 4 * HID * HARM) {
        int seg = idx / (HID * HARM);
        int off = idx - seg * (HID * HARM);
        const float* ph = (seg == 0) ? pq : (seg == 1) ? pk : (seg == 2) ? pv : po;
        const float* am = (seg == 0) ? aq : (seg == 1) ? ak : (seg == 2) ? av : ao;
        g_w[idx] = am[off] * cosf(ph[off]);
    } else {
        int j = idx - 4 * HID * HARM;
        if (j < 3 * HARM * HID) {
            int seg = j / (HARM * HID);
            int off = j - seg * (HARM * HID);
            g_bascat[j] = (seg == 0) ? bq[off] : (seg == 1) ? bk[off] : bv[off];
        }
    }
}

// ---------------- G_h = Wq_h^T Wk_h (stored transposed), C_h = Bo_h Wv_h -------
__global__ __launch_bounds__(256)
void gc_kernel(const float* __restrict__ bo) {
    int idx = blockIdx.x * 256 + threadIdx.x;
    const float* wq = g_w;
    const float* wk = g_w + HID * HARM;
    const float* wv = g_w + 2 * HID * HARM;
    if (idx < NH * HARM * HARM) {
        int h = idx >> 12, j = (idx >> 6) & 63, k = idx & 63;
        float s = 0.0f;
        for (int d = 0; d < DH; d++)
            s += wq[(h * DH + d) * HARM + k] * wk[(h * DH + d) * HARM + j];
        g_G[(h * HARM + j) * HARM + k] = s;
    } else {
        int e = idx - NH * HARM * HARM;
        if (e < HARM * NH * HARM) {
            int j = e >> 10, hi_ = e & 1023;
            int h = hi_ >> 6, i = hi_ & 63;
            float s = 0.0f;
            for (int d = 0; d < DH; d++)
                s += bo[j * HID + h * DH + d] * wv[(h * DH + d) * HARM + i];
            g_C[j * (NH * HARM) + h * HARM + i] = s;
        }
    }
}

// ---------------- generic SGEMM: C[M,N] = A[M,K] @ B[N,K]^T (fp32 out) -------
__global__ __launch_bounds__(256)
void sgemm_abT(const float* __restrict__ A, const float* __restrict__ B,
               float* __restrict__ C, int M, int N, int K,
               int lda, int ldb, int ldc) {
    __shared__ float As[16][68];
    __shared__ float Bs[16][68];
    const int tx = threadIdx.x, ty = threadIdx.y;
    const int tid = ty * 16 + tx;
    const int m0 = blockIdx.y * 64, n0 = blockIdx.x * 64;
    float acc[4][4] = {};
    for (int k0 = 0; k0 < K; k0 += 16) {
#pragma unroll
        for (int i = 0; i < 4; i++) {
            int e = tid + i * 256;
            int r = e >> 4, kk = e & 15;
            As[kk][r] = A[(size_t)(m0 + r) * lda + k0 + kk];
            Bs[kk][r] = B[(size_t)(n0 + r) * ldb + k0 + kk];
        }
        __syncthreads();
#pragma unroll
        for (int kk = 0; kk < 16; kk++) {
            float4 a4 = *reinterpret_cast<const float4*>(&As[kk][ty * 4]);
            float4 b4 = *reinterpret_cast<const float4*>(&Bs[kk][tx * 4]);
            float av[4] = {a4.x, a4.y, a4.z, a4.w};
            float bv[4] = {b4.x, b4.y, b4.z, b4.w};
#pragma unroll
            for (int i = 0; i < 4; i++)
#pragma unroll
                for (int j = 0; j < 4; j++)
                    acc[i][j] += av[i] * bv[j];
        }
        __syncthreads();
    }
#pragma unroll
    for (int i = 0; i < 4; i++) {
        int m = m0 + ty * 4 + i;
#pragma unroll
        for (int j = 0; j < 4; j++)
            C[(size_t)m * ldc + n0 + tx * 4 + j] = acc[i][j];
    }
}

// ---------------- T = Res_q @ G^T -> bf16 hi/lo (b,h,s,64) --------------------
__global__ __launch_bounds__(256)
void tproj_kernel() {
    __shared__ float As[16][68];
    __shared__ float Bs[16][68];
    const int tx = threadIdx.x, ty = threadIdx.y;
    const int tid = ty * 16 + tx;
    const int m0 = blockIdx.y * 64, n0 = blockIdx.x * 64;
    float acc[4][4] = {};
    for (int k0 = 0; k0 < HARM; k0 += 16) {
#pragma unroll
        for (int i = 0; i < 4; i++) {
            int e = tid + i * 256;
            int r = e >> 4, kk = e & 15;
            As[kk][r] = g_res[(size_t)(m0 + r) * (3 * HARM) + k0 + kk];
            Bs[kk][r] = g_G[(size_t)(n0 + r) * HARM + k0 + kk];
        }
        __syncthreads();
#pragma unroll
        for (int kk = 0; kk < 16; kk++) {
            float4 a4 = *reinterpret_cast<const float4*>(&As[kk][ty * 4]);
            float4 b4 = *reinterpret_cast<const float4*>(&Bs[kk][tx * 4]);
            float av[4] = {a4.x, a4.y, a4.z, a4.w};
            float bv[4] = {b4.x, b4.y, b4.z, b4.w};
#pragma unroll
            for (int i = 0; i < 4; i++)
#pragma unroll
                for (int j = 0; j < 4; j++)
                    acc[i][j] += av[i] * bv[j];
        }
        __syncthreads();
    }
#pragma unroll
    for (int i = 0; i < 4; i++) {
        int m = m0 + ty * 4 + i;
        int b = m >> 11, s = m & 2047;
#pragma unroll
        for (int j = 0; j < 4; j++) {
            int n = n0 + tx * 4 + j;
            int h = n >> 6, jj = n & 63;
            size_t idx = (((size_t)(b * NH + h)) * SEQ + s) * HARM + jj;
            float x = acc[i][j];
            __nv_bfloat16 hv = __float2bfloat16(x);
            __nv_bfloat16 lv = __float2bfloat16(x - __bfloat162float(hv));
            g_th[idx] = hv;
            g_tl[idx] = lv;
        }
    }
}

// ---------------- convert Res_k -> (b,s,64) hi/lo; Res_v -> (b,64,s) hi/lo ----
__global__ __launch_bounds__(256)
void convert_kernel() {
    int idx = blockIdx.x * 256 + threadIdx.x;
    const int NELE = MTOT * HARM;
    if (idx < NELE) {
        int m = idx >> 6, j = idx & 63;
        float x = g_res[(size_t)m * (3 * HARM) + HARM + j];
        __nv_bfloat16 hv = __float2bfloat16(x);
        g_rkh[idx] = hv;
        g_rkl[idx] = __float2bfloat16(x - __bfloat162float(hv));
    } else {
        int e = idx - NELE;
        if (e < NELE) {
            int m = e >> 6, j = e & 63;
            int b = m >> 11, s = m & 2047;
            float x = g_res[(size_t)m * (3 * HARM) + 2 * HARM + j];
            __nv_bfloat16 hv = __float2bfloat16(x);
            size_t o = ((size_t)b * HARM + j) * SEQ + s;
            g_rvh[o] = hv;
            g_rvl[o] = __float2bfloat16(x - __bfloat162float(hv));
        }
    }
}

// ---------------- mma.sync flash attention on factorized operands -------------
// S = T_h Res_k^T (K=64), U = P Res_v (N=64). grid(16, 32), 256 thr, occ 2.
#define BQ 128
#define BK 64
#define OFF_T  0                  // T hi 16KB, lo 16KB
#define OFF_B0 32768              // double buffers, 32KB each: rk_h, rk_l, rv_h, rv_l (8KB each)
#define BUFSZ  32768
#define FA_SMEM (OFF_B0 + 2*BUFSZ)   // 98304

__device__ __forceinline__ void prefetch_tile(uint32_t sb, int buf, int b, int kt, int tid) {
    const uint32_t base = sb + OFF_B0 + buf * BUFSZ;
    const __nv_bfloat16* rk_h = g_rkh + ((size_t)b * SEQ + kt * BK) * HARM;
    const __nv_bfloat16* rk_l = g_rkl + ((size_t)b * SEQ + kt * BK) * HARM;
#pragma unroll
    for (int i = 0; i < 2; i++) {
        int e = tid + i * 256;
        int row = e >> 3, cb = e & 7;                  // 64 rows x 8 chunks
        uint32_t off = row * 128 + ((cb ^ (row & 7)) << 4);
        cpasync16(base + off,        rk_h + row * HARM + cb * 8);
        cpasync16(base + 8192 + off, rk_l + row * HARM + cb * 8);
    }
    const __nv_bfloat16* rv_h = g_rvh + (size_t)b * HARM * SEQ + kt * BK;
    const __nv_bfloat16* rv_l = g_rvl + (size_t)b * HARM * SEQ + kt * BK;
#pragma unroll
    for (int i = 0; i < 2; i++) {
        int e = tid + i * 256;
        int row = e >> 3, cb = e & 7;                  // 64 rows (j) x 8 chunks (keys)
        uint32_t off = row * 128 + ((cb ^ (row & 7)) << 4);
        cpasync16(base + 16384 + off, rv_h + (size_t)row * SEQ + cb * 8);
        cpasync16(base + 24576 + off, rv_l + (size_t)row * SEQ + cb * 8);
    }
    CP_COMMIT();
}

__global__ __launch_bounds__(256, 2)
void flash_mma_kernel() {
    extern __shared__ char sm[];
    const uint32_t sb = smem_u32(sm);
    const int tid = threadIdx.x;
    const int lane = tid & 31, w = tid >> 5;
    const int bh = blockIdx.y;
    const int q0 = blockIdx.x * BQ;
    const int b = bh >> 4, h = bh & 15;
    const float K2 = 0.12751742f;   // (1/sqrt(128)) * log2(e)

    // ---- stage T tile (128 x 64 bf16 hi/lo, swizzled 128B rows) ----
    {
        const __nv_bfloat16* th = g_th + ((size_t)bh * SEQ + q0) * HARM;
        const __nv_bfloat16* tl = g_tl + ((size_t)bh * SEQ + q0) * HARM;
#pragma unroll
        for (int i = 0; i < 4; i++) {
            int e = tid + i * 256;
            int row = e >> 3, cb = e & 7;
            uint32_t off = row * 128 + ((cb ^ (row & 7)) << 4);
            *reinterpret_cast<uint4*>(sm + OFF_T + off) =
                *reinterpret_cast<const uint4*>(th + row * HARM + cb * 8);
            *reinterpret_cast<uint4*>(sm + OFF_T + 16384 + off) =
                *reinterpret_cast<const uint4*>(tl + row * HARM + cb * 8);
        }
    }
    prefetch_tile(sb, 0, b, 0, tid);
    __syncthreads();

    float U[8][4] = {};
    float rs0 = 0.0f, rs1 = 0.0f;
    float mx0 = -3.0e38f, mx1 = -3.0e38f;
    int buf = 0;

    for (int kt = 0; kt < SEQ / BK; kt++) {
        CP_WAIT0();
        __syncthreads();
        if (kt + 1 < SEQ / BK) prefetch_tile(sb, buf ^ 1, b, kt + 1, tid);

        const uint32_t kb = sb + OFF_B0 + buf * BUFSZ;

        // ---- S = T Res_k^T (hi*hi + lo*hi + hi*lo), K=64 ----
        float S[8][4] = {};
#pragma unroll
        for (int ks = 0; ks < 4; ks++) {
            int rowA = 16 * w + (lane & 15);
            int cbA = 2 * ks + (lane >> 4);
            uint32_t offA = rowA * 128 + ((cbA ^ (rowA & 7)) << 4);
            uint32_t th[4], tl[4];
            ldsm4(th, sb + OFF_T + offA);
            ldsm4(tl, sb + OFF_T + 16384 + offA);
#pragma unroll
            for (int nb = 0; nb < 4; nb++) {
                int rowB = nb * 16 + (lane & 15);
                uint32_t offB = rowB * 128 + (((2 * ks + (lane >> 4)) ^ (rowB & 7)) << 4);
                uint32_t kh[4], kl[4];
                ldsm4(kh, kb + offB);
                ldsm4(kl, kb + 8192 + offB);
                mma16816(S[2 * nb],     th, kh[0], kh[2]);
                mma16816(S[2 * nb + 1], th, kh[1], kh[3]);
                mma16816(S[2 * nb],     tl, kh[0], kh[2]);
                mma16816(S[2 * nb + 1], tl, kh[1], kh[3]);
                mma16816(S[2 * nb],     th, kl[0], kl[2]);
                mma16816(S[2 * nb + 1], th, kl[1], kl[3]);
            }
        }

        // ---- online softmax ----
        float tm0 = -3.0e38f, tm1 = -3.0e38f;
#pragma unroll
        for (int t = 0; t < 8; t++) {
            tm0 = fmaxf(tm0, fmaxf(S[t][0], S[t][1]));
            tm1 = fmaxf(tm1, fmaxf(S[t][2], S[t][3]));
        }
        tm0 = fmaxf(tm0, __shfl_xor_sync(0xffffffffu, tm0, 1));
        tm0 = fmaxf(tm0, __shfl_xor_sync(0xffffffffu, tm0, 2));
        tm1 = fmaxf(tm1, __shfl_xor_sync(0xffffffffu, tm1, 1));
        tm1 = fmaxf(tm1, __shfl_xor_sync(0xffffffffu, tm1, 2));

        float nm0 = fmaxf(mx0, tm0 * K2);
        float nm1 = fmaxf(mx1, tm1 * K2);
        float c0 = fast_exp2(mx0 - nm0);
        float c1 = fast_exp2(mx1 - nm1);
        mx0 = nm0; mx1 = nm1;

        float ls0 = 0.0f, ls1 = 0.0f;
#pragma unroll
        for (int t = 0; t < 8; t++) {
            float e0 = fast_exp2(S[t][0] * K2 - nm0);
            float e1 = fast_exp2(S[t][1] * K2 - nm0);
            float e2 = fast_exp2(S[t][2] * K2 - nm1);
            float e3 = fast_exp2(S[t][3] * K2 - nm1);
            ls0 += e0 + e1;
            ls1 += e2 + e3;
            S[t][0] = e0; S[t][1] = e1; S[t][2] = e2; S[t][3] = e3;
        }
        rs0 = rs0 * c0 + ls0;
        rs1 = rs1 * c1 + ls1;
#pragma unroll
        for (int t = 0; t < 8; t++) {
            U[t][0] *= c0; U[t][1] *= c0;
            U[t][2] *= c1; U[t][3] *= c1;
        }

        // ---- U += P Res_v (P in registers as A-fragments), N=64 ----
#pragma unroll
        for (int ks2 = 0; ks2 < 4; ks2++) {
            uint32_t ph[4], pl[4];
            ph[0] = cvt2(S[2 * ks2][1],     S[2 * ks2][0]);
            ph[1] = cvt2(S[2 * ks2][3],     S[2 * ks2][2]);
            ph[2] = cvt2(S[2 * ks2 + 1][1], S[2 * ks2 + 1][0]);
            ph[3] = cvt2(S[2 * ks2 + 1][3], S[2 * ks2 + 1][2]);
            pl[0] = cvt2(S[2 * ks2][1]     - bfhi_f(ph[0]), S[2 * ks2][0]     - bflo_f(ph[0]));
            pl[1] = cvt2(S[2 * ks2][3]     - bfhi_f(ph[1]), S[2 * ks2][2]     - bflo_f(ph[1]));
            pl[2] = cvt2(S[2 * ks2 + 1][1] - bfhi_f(ph[2]), S[2 * ks2 + 1][0] - bflo_f(ph[2]));
            pl[3] = cvt2(S[2 * ks2 + 1][3] - bfhi_f(ph[3]), S[2 * ks2 + 1][2] - bflo_f(ph[3]));
#pragma unroll
            for (int nb = 0; nb < 4; nb++) {
                int rowB = nb * 16 + (lane & 15);
                uint32_t offB = rowB * 128 + (((2 * ks2 + (lane >> 4)) ^ (rowB & 7)) << 4);
                uint32_t vh[4], vl[4];
                ldsm4(vh, kb + 16384 + offB);
                ldsm4(vl, kb + 24576 + offB);
                mma16816(U[2 * nb],     ph, vh[0], vh[2]);
                mma16816(U[2 * nb + 1], ph, vh[1], vh[3]);
                mma16816(U[2 * nb],     ph, vl[0], vl[2]);
                mma16816(U[2 * nb + 1], ph, vl[1], vl[3]);
                mma16816(U[2 * nb],     pl, vh[0], vh[2]);
                mma16816(U[2 * nb + 1], pl, vh[1], vh[3]);
            }
        }
        buf ^= 1;
    }

    // ---- epilogue: normalize, store U to (b,s,h,64) fp32 ----
    rs0 += __shfl_xor_sync(0xffffffffu, rs0, 1);
    rs0 += __shfl_xor_sync(0xffffffffu, rs0, 2);
    rs1 += __shfl_xor_sync(0xffffffffu, rs1, 1);
    rs1 += __shfl_xor_sync(0xffffffffu, rs1, 2);
    const float inv0 = 1.0f / rs0;
    const float inv1 = 1.0f / rs1;

    const int row0 = q0 + 16 * w + (lane >> 2);
    float* u0 = g_u + (((size_t)b * SEQ + row0) * NH + h) * HARM + (lane & 3) * 2;
    float* u1 = u0 + 8 * (size_t)NH * HARM;
#pragma unroll
    for (int nb = 0; nb < 4; nb++) {
        *reinterpret_cast<float2*>(u0 + nb * 16) =
            make_float2(U[2 * nb][0] * inv0, U[2 * nb][1] * inv0);
        *reinterpret_cast<float2*>(u1 + nb * 16) =
            make_float2(U[2 * nb][2] * inv1, U[2 * nb][3] * inv1);
        *reinterpret_cast<float2*>(u0 + nb * 16 + 8) =
            make_float2(U[2 * nb + 1][0] * inv0, U[2 * nb + 1][1] * inv0);
        *reinterpret_cast<float2*>(u1 + nb * 16 + 8) =
            make_float2(U[2 * nb + 1][2] * inv1, U[2 * nb + 1][3] * inv1);
    }
}

// ---------------- launcher ----------------------------------------------------
extern "C" void kernel_launch(void* const* d_in, const int* in_sizes, int n_in,
                              void* d_out, int out_size) {
    const float* x  = (const float*)d_in[0];
    const float* bq = (const float*)d_in[1];
    const float* pq = (const float*)d_in[2];
    const float* aq = (const float*)d_in[3];
    const float* bk = (const float*)d_in[4];
    const float* pk = (const float*)d_in[5];
    const float* ak = (const float*)d_in[6];
    const float* bv = (const float*)d_in[7];
    const float* pv = (const float*)d_in[8];
    const float* av = (const float*)d_in[9];
    const float* bo = (const float*)d_in[10];
    const float* po = (const float*)d_in[11];
    const float* ao = (const float*)d_in[12];
    float* out = (float*)d_out;

    float *w, *bascat, *res, *u, *reso, *Cc;
    cudaGetSymbolAddress((void**)&w,      g_w);
    cudaGetSymbolAddress((void**)&bascat, g_bascat);
    cudaGetSymbolAddress((void**)&res,    g_res);
    cudaGetSymbolAddress((void**)&u,      g_u);
    cudaGetSymbolAddress((void**)&reso,   g_reso);
    cudaGetSymbolAddress((void**)&Cc,     g_C);

    // 1: weights + basis concat
    prep_kernel<<<(7 * HID * HARM + 255) / 256, 256>>>(pq, aq, pk, ak, pv, av, po, ao,
                                                       bq, bk, bv);
    // 2: per-head G (transposed) and C
    gc_kernel<<<(2 * NH * HARM * HARM + 255) / 256, 256>>>(bo);

    dim3 thr(16, 16);
    // 3: resonances q|k|v (4096 x 192)
    sgemm_abT<<<dim3(3, MTOT / 64), thr>>>(x, bascat, res,
                                           MTOT, 3 * HARM, HID, HID, HID, 3 * HARM);
    // 4: T = Res_q G^T -> bf16 hi/lo (b,h,s,64)
    tproj_kernel<<<dim3(NH * HARM / 64, MTOT / 64), thr>>>();
    // 5: Res_k/Res_v -> bf16 hi/lo (+ V transpose)
    convert_kernel<<<(2 * MTOT * HARM + 255) / 256, 256>>>();

    // 6: attention on factorized operands
    cudaFuncSetAttribute(flash_mma_kernel,
                         cudaFuncAttributeMaxDynamicSharedMemorySize, FA_SMEM);
    flash_mma_kernel<<<dim3(SEQ / BQ, BATCH * NH), 256, FA_SMEM>>>();

    // 7: res_o = U_cat @ C_cat^T   (4096 x 64, K=1024)
    sgemm_abT<<<dim3(1, MTOT / 64), thr>>>(u, Cc, reso,
                                           MTOT, HARM, NH * HARM,
                                           NH * HARM, NH * HARM, HARM);
    // 8: out = res_o @ Wo^T
    sgemm_abT<<<dim3(HID / 64, MTOT / 64), thr>>>(reso, w + 3 * HID * HARM, out,
                                                  MTOT, HID, HARM, HARM, HARM, HID);
}